// round 1
// baseline (speedup 1.0000x reference)
#include <cuda_runtime.h>
#include <math.h>
#include <stdint.h>

#define BATCH 4
#define SLEN  2048
#define EMBED 1024
#define NHEAD 16
#define HDIM  64
#define NTOK  (BATCH * SLEN)     // 8192
#define QKVN  (3 * EMBED)        // 3072

// Scratch (static device globals — allocation APIs are forbidden)
__device__ float g_Q[(size_t)BATCH * NHEAD * SLEN * HDIM];
__device__ float g_K[(size_t)BATCH * NHEAD * SLEN * HDIM];
__device__ float g_V[(size_t)BATCH * NHEAD * SLEN * HDIM];
__device__ float g_O[(size_t)NTOK * EMBED];

// ---------------------------------------------------------------------------
// SGEMM: C[M,N] = A[M,K] @ B[K,N], 128x128 tile, BK=8, 256 threads, 8x8/thread
// MODE 0: scatter epilogue into Q/K/V (de-interleave h/d/which packing)
// MODE 1: plain store to C
// ---------------------------------------------------------------------------
template <int MODE>
__global__ void __launch_bounds__(256)
sgemm_kernel(const float* __restrict__ A, const float* __restrict__ B,
             float* __restrict__ C,
             float* __restrict__ Qo, float* __restrict__ Ko, float* __restrict__ Vo,
             int M, int N, int K)
{
    __shared__ float As[8][132];   // padded: conflict-free transposed stores
    __shared__ float Bs[8][128];

    const int tid = threadIdx.x;
    const int tx = tid & 15;          // 0..15
    const int ty = tid >> 4;          // 0..15
    const int bm = blockIdx.y;
    const int bn = blockIdx.x;

    const float* Ablk = A + (size_t)bm * 128 * K;
    const float* Bblk = B + (size_t)bn * 128;

    const int arow = tid >> 1;            // 0..127
    const int acol = (tid & 1) * 4;       // 0 or 4
    const int brow = tid >> 5;            // 0..7
    const int bcol = (tid & 31) * 4;      // 0..124

    float acc[8][8];
#pragma unroll
    for (int i = 0; i < 8; i++)
#pragma unroll
        for (int j = 0; j < 8; j++) acc[i][j] = 0.0f;

    for (int k0 = 0; k0 < K; k0 += 8) {
        float4 av = *(const float4*)(Ablk + (size_t)arow * K + k0 + acol);
        float4 bv = *(const float4*)(Bblk + (size_t)(k0 + brow) * N + bcol);

        __syncthreads();
        As[acol + 0][arow] = av.x;
        As[acol + 1][arow] = av.y;
        As[acol + 2][arow] = av.z;
        As[acol + 3][arow] = av.w;
        *(float4*)&Bs[brow][bcol] = bv;
        __syncthreads();

#pragma unroll
        for (int kk = 0; kk < 8; kk++) {
            float4 a0 = *(const float4*)&As[kk][ty * 8];
            float4 a1 = *(const float4*)&As[kk][ty * 8 + 4];
            float4 b0 = *(const float4*)&Bs[kk][tx * 4];        // cols tx*4 .. +3
            float4 b1 = *(const float4*)&Bs[kk][64 + tx * 4];   // cols 64+tx*4 ..
            float a[8] = {a0.x, a0.y, a0.z, a0.w, a1.x, a1.y, a1.z, a1.w};
            float b[8] = {b0.x, b0.y, b0.z, b0.w, b1.x, b1.y, b1.z, b1.w};
#pragma unroll
            for (int i = 0; i < 8; i++)
#pragma unroll
                for (int j = 0; j < 8; j++) acc[i][j] = fmaf(a[i], b[j], acc[i][j]);
        }
    }

    if (MODE == 0) {
        // de-interleave: col c -> h = c/192, d = (c%192)/3, which = c%3
#pragma unroll
        for (int i = 0; i < 8; i++) {
            int row = bm * 128 + ty * 8 + i;        // token index
            int b_  = row >> 11;                    // /2048
            int s   = row & 2047;
#pragma unroll
            for (int j = 0; j < 8; j++) {
                int col = bn * 128 + ((j < 4) ? (tx * 4 + j) : (64 + tx * 4 + j - 4));
                int h   = col / 192;
                int rem = col - h * 192;
                int d   = rem / 3;
                int w   = rem - d * 3;
                float* dst = (w == 0) ? Qo : (w == 1) ? Ko : Vo;
                dst[(((size_t)b_ * NHEAD + h) * SLEN + s) * HDIM + d] = acc[i][j];
            }
        }
    } else {
#pragma unroll
        for (int i = 0; i < 8; i++) {
            size_t row = (size_t)(bm * 128 + ty * 8 + i);
            float4 v0 = make_float4(acc[i][0], acc[i][1], acc[i][2], acc[i][3]);
            float4 v1 = make_float4(acc[i][4], acc[i][5], acc[i][6], acc[i][7]);
            *(float4*)&C[row * N + bn * 128 + tx * 4]      = v0;
            *(float4*)&C[row * N + bn * 128 + 64 + tx * 4] = v1;
        }
    }
}

// ---------------------------------------------------------------------------
// Flash attention, fp32. BQ = BK = 64, D = 64. 256 threads.
// thread (ty,tx): score rows ty*4+a (a<4), score cols tx+16*b (b<4).
// O accumulator: rows ty*4+a, d-cols tx+16*b.
// grid.x = SLEN/64 q-blocks, grid.y = BATCH*NHEAD.
// ---------------------------------------------------------------------------
#define LD 68   // padded row stride (floats)

__global__ void __launch_bounds__(256)
attn_kernel(const float* __restrict__ Q, const float* __restrict__ K,
            const float* __restrict__ V, float* __restrict__ O)
{
    extern __shared__ float sm[];
    float* Qs = sm;                // [64][LD]
    float* Ks = Qs + 64 * LD;
    float* Vs = Ks + 64 * LD;
    float* Ps = Vs + 64 * LD;

    const int tid = threadIdx.x;
    const int tx = tid & 15;
    const int ty = tid >> 4;
    const int qblk = blockIdx.x;
    const int bh   = blockIdx.y;

    const float* Qg = Q + ((size_t)bh * SLEN + qblk * 64) * HDIM;
    const float* Kg = K + (size_t)bh * SLEN * HDIM;
    const float* Vg = V + (size_t)bh * SLEN * HDIM;

    const float qscale = 1.0f / 32.0f;   // 1/sqrt(EMBED) = 1/sqrt(1024)

    // load Q block (scaled)
#pragma unroll
    for (int i = 0; i < 4; i++) {
        int f4  = tid + i * 256;          // 0..1023
        int row = f4 >> 4;
        int c4  = (f4 & 15) * 4;
        float4 v = *(const float4*)(Qg + row * HDIM + c4);
        v.x *= qscale; v.y *= qscale; v.z *= qscale; v.w *= qscale;
        *(float4*)&Qs[row * LD + c4] = v;
    }

    float m[4], l[4], acc[4][4];
#pragma unroll
    for (int a = 0; a < 4; a++) {
        m[a] = -1e30f; l[a] = 0.0f;
#pragma unroll
        for (int b = 0; b < 4; b++) acc[a][b] = 0.0f;
    }

    for (int kb = 0; kb < SLEN / 64; kb++) {
        __syncthreads();   // previous iteration's smem reads complete
        const float* Kgb = Kg + (size_t)kb * 64 * HDIM;
        const float* Vgb = Vg + (size_t)kb * 64 * HDIM;
#pragma unroll
        for (int i = 0; i < 4; i++) {
            int f4  = tid + i * 256;
            int row = f4 >> 4;
            int c4  = (f4 & 15) * 4;
            *(float4*)&Ks[row * LD + c4] = *(const float4*)(Kgb + row * HDIM + c4);
            *(float4*)&Vs[row * LD + c4] = *(const float4*)(Vgb + row * HDIM + c4);
        }
        __syncthreads();

        // S = Qs @ Ks^T  (4x4 per thread)
        float S[4][4];
#pragma unroll
        for (int a = 0; a < 4; a++)
#pragma unroll
            for (int b = 0; b < 4; b++) S[a][b] = 0.0f;

#pragma unroll
        for (int d4 = 0; d4 < HDIM; d4 += 4) {
            float4 qv[4], kv[4];
#pragma unroll
            for (int a = 0; a < 4; a++) qv[a] = *(const float4*)&Qs[(ty * 4 + a) * LD + d4];
#pragma unroll
            for (int b = 0; b < 4; b++) kv[b] = *(const float4*)&Ks[(tx + 16 * b) * LD + d4];
#pragma unroll
            for (int a = 0; a < 4; a++)
#pragma unroll
                for (int b = 0; b < 4; b++) {
                    S[a][b] = fmaf(qv[a].x, kv[b].x, S[a][b]);
                    S[a][b] = fmaf(qv[a].y, kv[b].y, S[a][b]);
                    S[a][b] = fmaf(qv[a].z, kv[b].z, S[a][b]);
                    S[a][b] = fmaf(qv[a].w, kv[b].w, S[a][b]);
                }
        }

        // online softmax (row groups = 16 lanes sharing ty)
#pragma unroll
        for (int a = 0; a < 4; a++) {
            float rm = fmaxf(fmaxf(S[a][0], S[a][1]), fmaxf(S[a][2], S[a][3]));
#pragma unroll
            for (int off = 8; off >= 1; off >>= 1)
                rm = fmaxf(rm, __shfl_xor_sync(0xffffffffu, rm, off, 16));
            float mn = fmaxf(m[a], rm);
            float alpha = __expf(m[a] - mn);
            m[a] = mn;
            l[a] *= alpha;
#pragma unroll
            for (int b = 0; b < 4; b++) acc[a][b] *= alpha;
            float ps = 0.0f;
#pragma unroll
            for (int b = 0; b < 4; b++) {
                S[a][b] = __expf(S[a][b] - mn);
                ps += S[a][b];
            }
            l[a] += ps;   // partial over this thread's cols; reduced at end
#pragma unroll
            for (int b = 0; b < 4; b++)
                Ps[(ty * 4 + a) * LD + tx + 16 * b] = S[a][b];
        }
        __syncthreads();

        // O += P @ V
#pragma unroll 8
        for (int j = 0; j < 64; j++) {
            float vv[4], pv[4];
#pragma unroll
            for (int b = 0; b < 4; b++) vv[b] = Vs[j * LD + tx + 16 * b];
#pragma unroll
            for (int a = 0; a < 4; a++) pv[a] = Ps[(ty * 4 + a) * LD + j];
#pragma unroll
            for (int a = 0; a < 4; a++)
#pragma unroll
                for (int b = 0; b < 4; b++) acc[a][b] = fmaf(pv[a], vv[b], acc[a][b]);
        }
    }

    // finalize: reduce l across the 16-lane row group, normalize, store
    const int b_ = bh >> 4;
    const int h  = bh & 15;
#pragma unroll
    for (int a = 0; a < 4; a++) {
        float ls = l[a];
#pragma unroll
        for (int off = 8; off >= 1; off >>= 1)
            ls += __shfl_xor_sync(0xffffffffu, ls, off, 16);
        float inv = 1.0f / ls;
        int srow = qblk * 64 + ty * 4 + a;
        float* dst = O + ((size_t)b_ * SLEN + srow) * EMBED + h * HDIM;
#pragma unroll
        for (int b = 0; b < 4; b++)
            dst[tx + 16 * b] = acc[a][b] * inv;
    }
}

// ---------------------------------------------------------------------------
extern "C" void kernel_launch(void* const* d_in, const int* in_sizes, int n_in,
                              void* d_out, int out_size)
{
    const float* x    = (const float*)d_in[0];   // [4,2048,1024]
    const float* Wqkv = (const float*)d_in[1];   // [1024,3072]
    const float* Wout = (const float*)d_in[2];   // [1024,1024]
    float* out = (float*)d_out;                  // [4,2048,1024]

    float *Qp, *Kp, *Vp, *Op;
    cudaGetSymbolAddress((void**)&Qp, g_Q);
    cudaGetSymbolAddress((void**)&Kp, g_K);
    cudaGetSymbolAddress((void**)&Vp, g_V);
    cudaGetSymbolAddress((void**)&Op, g_O);

    const int attn_smem = 4 * 64 * LD * sizeof(float);   // 69632 B
    cudaFuncSetAttribute(attn_kernel, cudaFuncAttributeMaxDynamicSharedMemorySize, attn_smem);

    // 1) QKV projection + de-interleave into Q/K/V [b,h,s,d]
    dim3 g1(QKVN / 128, NTOK / 128);   // (24, 64)
    sgemm_kernel<0><<<g1, 256>>>(x, Wqkv, nullptr, Qp, Kp, Vp, NTOK, QKVN, EMBED);

    // 2) attention -> g_O laid out [token, E] (heads re-merged)
    dim3 g2(SLEN / 64, BATCH * NHEAD); // (32, 64)
    attn_kernel<<<g2, 256, attn_smem>>>(Qp, Kp, Vp, Op);

    // 3) output projection
    dim3 g3(EMBED / 128, NTOK / 128);  // (8, 64)
    sgemm_kernel<1><<<g3, 256>>>(Op, Wout, out, nullptr, nullptr, nullptr, NTOK, EMBED, EMBED);
}

// round 2
// speedup vs baseline: 1.5561x; 1.5561x over previous
#include <cuda_runtime.h>
#include <stdint.h>
#include <math.h>

#define BATCH 4
#define SLEN  2048
#define EMBED 1024
#define NHEAD 16
#define HDIM  64
#define NTOK  (BATCH * SLEN)     // 8192
#define QKVN  (3 * EMBED)        // 3072

// Scratch (static device globals — allocation APIs are forbidden)
__device__ float g_Q[(size_t)BATCH * NHEAD * SLEN * HDIM];
__device__ float g_K[(size_t)BATCH * NHEAD * SLEN * HDIM];
__device__ float g_V[(size_t)BATCH * NHEAD * SLEN * HDIM];
__device__ float g_O[(size_t)NTOK * EMBED];

// ---------------------------------------------------------------------------
// tf32 helpers
// ---------------------------------------------------------------------------
__device__ __forceinline__ uint32_t f2tf32(float f) {
    uint32_t r;
    asm("cvt.rna.tf32.f32 %0, %1;" : "=r"(r) : "f"(f));
    return r;
}

__device__ __forceinline__ void mma_tf32(float* d, const uint32_t* a, const uint32_t* b) {
    asm volatile(
        "mma.sync.aligned.m16n8k8.row.col.f32.tf32.tf32.f32 "
        "{%0,%1,%2,%3},{%4,%5,%6,%7},{%8,%9},{%0,%1,%2,%3};"
        : "+f"(d[0]), "+f"(d[1]), "+f"(d[2]), "+f"(d[3])
        : "r"(a[0]), "r"(a[1]), "r"(a[2]), "r"(a[3]), "r"(b[0]), "r"(b[1]));
}

// ---------------------------------------------------------------------------
// 3xTF32 GEMM: C[M,N] = A[M,K] @ B[K,N].  BM=BN=128, BK=16, 256 threads.
// 8 warps = 2(M) x 4(N); warp tile 64x32; per warp 4 m-tiles x 4 n-tiles.
// hi/lo split: D += Ah*Bh + Ah*Bl + Al*Bh  (fp32-class accuracy).
// MODE 0: scatter epilogue de-interleaving (H, D, 3) packing into Q/K/V.
// MODE 1: plain float2 stores into C.
// ---------------------------------------------------------------------------
template <int MODE>
__global__ void __launch_bounds__(256)
gemm3x_kernel(const float* __restrict__ A, const float* __restrict__ B,
              float* __restrict__ C,
              float* __restrict__ Qo, float* __restrict__ Ko, float* __restrict__ Vo,
              int M, int N, int K)
{
    __shared__ uint32_t Ah[16][132], Al[16][132];   // k-major (transposed) A
    __shared__ uint32_t Bh[16][132], Bl[16][132];   // k-major B

    const int tid  = threadIdx.x;
    const int lane = tid & 31;
    const int warp = tid >> 5;
    const int wm = warp >> 2;          // 0..1
    const int wn = warp & 3;           // 0..3
    const int g  = lane >> 2;          // group id 0..7
    const int t  = lane & 3;           // thread-in-group 0..3
    const int bm = blockIdx.y;
    const int bn = blockIdx.x;

    const float* Ab = A + (size_t)bm * 128 * K;
    const float* Bb = B + (size_t)bn * 128;

    float acc[4][4][4];
#pragma unroll
    for (int mt = 0; mt < 4; mt++)
#pragma unroll
        for (int nt = 0; nt < 4; nt++)
#pragma unroll
            for (int e = 0; e < 4; e++) acc[mt][nt][e] = 0.0f;

    for (int k0 = 0; k0 < K; k0 += 16) {
        float4 av[2], bv[2];
#pragma unroll
        for (int r = 0; r < 2; r++) {
            int i = tid + r * 256;
            int arow = i >> 2, ac = (i & 3) * 4;
            av[r] = *(const float4*)(Ab + (size_t)arow * K + k0 + ac);
            int brow = i >> 5, bc = (i & 31) * 4;
            bv[r] = *(const float4*)(Bb + (size_t)(k0 + brow) * N + bc);
        }
        __syncthreads();
#pragma unroll
        for (int r = 0; r < 2; r++) {
            int i = tid + r * 256;
            int arow = i >> 2, ac = (i & 3) * 4;
            float va[4] = {av[r].x, av[r].y, av[r].z, av[r].w};
#pragma unroll
            for (int j = 0; j < 4; j++) {
                uint32_t hi = f2tf32(va[j]);
                uint32_t lo = f2tf32(va[j] - __uint_as_float(hi));
                Ah[ac + j][arow] = hi;
                Al[ac + j][arow] = lo;
            }
            int brow = i >> 5, bc = (i & 31) * 4;
            float vb[4] = {bv[r].x, bv[r].y, bv[r].z, bv[r].w};
            uint4 bh4, bl4;
            {
                uint32_t h0 = f2tf32(vb[0]), h1 = f2tf32(vb[1]), h2 = f2tf32(vb[2]), h3 = f2tf32(vb[3]);
                bh4 = make_uint4(h0, h1, h2, h3);
                bl4 = make_uint4(f2tf32(vb[0] - __uint_as_float(h0)),
                                 f2tf32(vb[1] - __uint_as_float(h1)),
                                 f2tf32(vb[2] - __uint_as_float(h2)),
                                 f2tf32(vb[3] - __uint_as_float(h3)));
            }
            *(uint4*)&Bh[brow][bc] = bh4;
            *(uint4*)&Bl[brow][bc] = bl4;
        }
        __syncthreads();

#pragma unroll
        for (int ks = 0; ks < 2; ks++) {
            const int kb = ks * 8;
            uint32_t ah[4][4], al[4][4], bh[4][2], bl[4][2];
#pragma unroll
            for (int mt = 0; mt < 4; mt++) {
                int m0 = wm * 64 + mt * 16 + g;
                int kk = kb + t;
                ah[mt][0] = Ah[kk][m0];     ah[mt][1] = Ah[kk][m0 + 8];
                ah[mt][2] = Ah[kk + 4][m0]; ah[mt][3] = Ah[kk + 4][m0 + 8];
                al[mt][0] = Al[kk][m0];     al[mt][1] = Al[kk][m0 + 8];
                al[mt][2] = Al[kk + 4][m0]; al[mt][3] = Al[kk + 4][m0 + 8];
            }
#pragma unroll
            for (int nt = 0; nt < 4; nt++) {
                int n0 = wn * 32 + nt * 8 + g;
                bh[nt][0] = Bh[kb + t][n0];     bh[nt][1] = Bh[kb + t + 4][n0];
                bl[nt][0] = Bl[kb + t][n0];     bl[nt][1] = Bl[kb + t + 4][n0];
            }
#pragma unroll
            for (int mt = 0; mt < 4; mt++)
#pragma unroll
                for (int nt = 0; nt < 4; nt++) {
                    mma_tf32(acc[mt][nt], ah[mt], bh[nt]);
                    mma_tf32(acc[mt][nt], ah[mt], bl[nt]);
                    mma_tf32(acc[mt][nt], al[mt], bh[nt]);
                }
        }
    }

    if (MODE == 0) {
#pragma unroll
        for (int mt = 0; mt < 4; mt++)
#pragma unroll
            for (int nt = 0; nt < 4; nt++) {
                int r0 = bm * 128 + wm * 64 + mt * 16 + g;
                int c0 = bn * 128 + wn * 32 + nt * 8 + 2 * t;
#pragma unroll
                for (int e = 0; e < 4; e++) {
                    int row = r0 + (e >> 1) * 8;
                    int col = c0 + (e & 1);
                    int b_  = row >> 11;
                    int s   = row & 2047;
                    int h   = col / 192;
                    int rem = col - h * 192;
                    int d   = rem / 3;
                    int w   = rem - d * 3;
                    float* dst = (w == 0) ? Qo : (w == 1) ? Ko : Vo;
                    dst[(((size_t)b_ * NHEAD + h) * SLEN + s) * HDIM + d] = acc[mt][nt][e];
                }
            }
    } else {
#pragma unroll
        for (int mt = 0; mt < 4; mt++)
#pragma unroll
            for (int nt = 0; nt < 4; nt++) {
                size_t r = (size_t)(bm * 128 + wm * 64 + mt * 16 + g);
                int    c = bn * 128 + wn * 32 + nt * 8 + 2 * t;
                *(float2*)&C[r * N + c]       = make_float2(acc[mt][nt][0], acc[mt][nt][1]);
                *(float2*)&C[(r + 8) * N + c] = make_float2(acc[mt][nt][2], acc[mt][nt][3]);
            }
    }
}

// ---------------------------------------------------------------------------
// Flash attention, tf32 tensor cores. BQ=128, BKEY=64, D=64. 256 thr = 8 warps.
// Warps 4(q) x 2(col): warp tile 32 rows x 32 cols for both S and O.
// Softmax in fp32 by row-owner threads (2 threads/row); P stored as tf32 bits.
// ---------------------------------------------------------------------------
#define LDA 68   // u32 stride for all smem tiles

__global__ void __launch_bounds__(256)
attn_tc_kernel(const float* __restrict__ Q, const float* __restrict__ K,
               const float* __restrict__ V, float* __restrict__ O)
{
    extern __shared__ uint32_t smu[];
    uint32_t* Qs = smu;                      // [128][LDA] tf32
    uint32_t* Ks = Qs + 128 * LDA;           // [64][LDA]  tf32
    uint32_t* Vs = Ks + 64 * LDA;            // [64][LDA]  tf32
    float*    Ssf = (float*)(Vs + 64 * LDA); // [128][LDA] fp32 scores -> tf32 P
    uint32_t* Psu = (uint32_t*)Ssf;
    float*    alpha_sm = Ssf + 128 * LDA;    // [128]
    float*    linv_sm  = alpha_sm + 128;     // [128]

    const int tid  = threadIdx.x;
    const int lane = tid & 31;
    const int warp = tid >> 5;
    const int wq = warp >> 1;                // 0..3 (row block)
    const int wk = warp & 1;                 // 0..1 (col block)
    const int g  = lane >> 2;
    const int t  = lane & 3;
    const int qblk = blockIdx.x;
    const int bh   = blockIdx.y;

    const float* Qg = Q + ((size_t)bh * SLEN + qblk * 128) * HDIM;
    const float* Kg = K + (size_t)bh * SLEN * HDIM;
    const float* Vg = V + (size_t)bh * SLEN * HDIM;
    const float qscale = 1.0f / 32.0f;       // 1/sqrt(1024)

    // load Q once (scaled, tf32)
#pragma unroll
    for (int r = 0; r < 8; r++) {
        int i = tid + r * 256;               // 0..2047
        int row = i >> 4, c4 = (i & 15) * 4;
        float4 v = *(const float4*)(Qg + (size_t)row * HDIM + c4);
        Qs[row * LDA + c4 + 0] = f2tf32(v.x * qscale);
        Qs[row * LDA + c4 + 1] = f2tf32(v.y * qscale);
        Qs[row * LDA + c4 + 2] = f2tf32(v.z * qscale);
        Qs[row * LDA + c4 + 3] = f2tf32(v.w * qscale);
    }

    // softmax row-owner state: row = tid>>1, half = tid&1
    const int srow = tid >> 1;
    const int shf  = tid & 1;
    float m_r = -1e30f, l_r = 0.0f;

    // O accumulators: [mt 2][nt 4][4]
    float acc[2][4][4];
#pragma unroll
    for (int mt = 0; mt < 2; mt++)
#pragma unroll
        for (int nt = 0; nt < 4; nt++)
#pragma unroll
            for (int e = 0; e < 4; e++) acc[mt][nt][e] = 0.0f;

    for (int kb = 0; kb < SLEN / 64; kb++) {
        __syncthreads();   // previous iteration's Ps/Vs reads done
        const float* Kgb = Kg + (size_t)kb * 64 * HDIM;
        const float* Vgb = Vg + (size_t)kb * 64 * HDIM;
#pragma unroll
        for (int r = 0; r < 4; r++) {
            int i = tid + r * 256;           // 0..1023
            int row = i >> 4, c4 = (i & 15) * 4;
            float4 kv = *(const float4*)(Kgb + (size_t)row * HDIM + c4);
            float4 vv = *(const float4*)(Vgb + (size_t)row * HDIM + c4);
            Ks[row * LDA + c4 + 0] = f2tf32(kv.x);
            Ks[row * LDA + c4 + 1] = f2tf32(kv.y);
            Ks[row * LDA + c4 + 2] = f2tf32(kv.z);
            Ks[row * LDA + c4 + 3] = f2tf32(kv.w);
            Vs[row * LDA + c4 + 0] = f2tf32(vv.x);
            Vs[row * LDA + c4 + 1] = f2tf32(vv.y);
            Vs[row * LDA + c4 + 2] = f2tf32(vv.z);
            Vs[row * LDA + c4 + 3] = f2tf32(vv.w);
        }
        __syncthreads();

        // S = Qs @ Ks^T
        float s[2][4][4];
#pragma unroll
        for (int mt = 0; mt < 2; mt++)
#pragma unroll
            for (int nt = 0; nt < 4; nt++)
#pragma unroll
                for (int e = 0; e < 4; e++) s[mt][nt][e] = 0.0f;

#pragma unroll
        for (int ks = 0; ks < 8; ks++) {
            const int kb2 = ks * 8;
            uint32_t aq[2][4];
#pragma unroll
            for (int mt = 0; mt < 2; mt++) {
                int m0 = wq * 32 + mt * 16 + g;
                int kk = kb2 + t;
                aq[mt][0] = Qs[m0 * LDA + kk];
                aq[mt][1] = Qs[(m0 + 8) * LDA + kk];
                aq[mt][2] = Qs[m0 * LDA + kk + 4];
                aq[mt][3] = Qs[(m0 + 8) * LDA + kk + 4];
            }
#pragma unroll
            for (int nt = 0; nt < 4; nt++) {
                int n0 = wk * 32 + nt * 8 + g;
                uint32_t bk[2];
                bk[0] = Ks[n0 * LDA + kb2 + t];
                bk[1] = Ks[n0 * LDA + kb2 + 4 + t];
                mma_tf32(s[0][nt], aq[0], bk);
                mma_tf32(s[1][nt], aq[1], bk);
            }
        }

        // write scores (fp32)
#pragma unroll
        for (int mt = 0; mt < 2; mt++)
#pragma unroll
            for (int nt = 0; nt < 4; nt++) {
                int r0 = wq * 32 + mt * 16 + g;
                int c0 = wk * 32 + nt * 8 + 2 * t;
                Ssf[r0 * LDA + c0]           = s[mt][nt][0];
                Ssf[r0 * LDA + c0 + 1]       = s[mt][nt][1];
                Ssf[(r0 + 8) * LDA + c0]     = s[mt][nt][2];
                Ssf[(r0 + 8) * LDA + c0 + 1] = s[mt][nt][3];
            }
        __syncthreads();

        // online softmax: 2 threads per row
        {
            float* rowp = Ssf + srow * LDA + shf * 32;
            float4* rp4 = (float4*)rowp;
            float mx = -1e30f;
#pragma unroll
            for (int j = 0; j < 8; j++) {
                float4 v = rp4[j];
                mx = fmaxf(mx, fmaxf(fmaxf(v.x, v.y), fmaxf(v.z, v.w)));
            }
            mx = fmaxf(mx, __shfl_xor_sync(0xffffffffu, mx, 1));
            float mn = fmaxf(m_r, mx);
            float alpha = __expf(m_r - mn);
            m_r = mn;
            float sum = 0.0f;
            uint4* rpu = (uint4*)rowp;
#pragma unroll
            for (int j = 0; j < 8; j++) {
                float4 v = rp4[j];
                float e0 = __expf(v.x - mn), e1 = __expf(v.y - mn);
                float e2 = __expf(v.z - mn), e3 = __expf(v.w - mn);
                sum += (e0 + e1) + (e2 + e3);
                rpu[j] = make_uint4(f2tf32(e0), f2tf32(e1), f2tf32(e2), f2tf32(e3));
            }
            sum += __shfl_xor_sync(0xffffffffu, sum, 1);
            l_r = l_r * alpha + sum;
            if (shf == 0) alpha_sm[srow] = alpha;
        }
        __syncthreads();

        // rescale O accumulators, then O += P @ V
#pragma unroll
        for (int mt = 0; mt < 2; mt++) {
            int r0 = wq * 32 + mt * 16 + g;
            float a0 = alpha_sm[r0], a1 = alpha_sm[r0 + 8];
#pragma unroll
            for (int nt = 0; nt < 4; nt++) {
                acc[mt][nt][0] *= a0; acc[mt][nt][1] *= a0;
                acc[mt][nt][2] *= a1; acc[mt][nt][3] *= a1;
            }
        }
#pragma unroll
        for (int ks = 0; ks < 8; ks++) {
            const int kb2 = ks * 8;
            uint32_t ap[2][4];
#pragma unroll
            for (int mt = 0; mt < 2; mt++) {
                int m0 = wq * 32 + mt * 16 + g;
                int kk = kb2 + t;
                ap[mt][0] = Psu[m0 * LDA + kk];
                ap[mt][1] = Psu[(m0 + 8) * LDA + kk];
                ap[mt][2] = Psu[m0 * LDA + kk + 4];
                ap[mt][3] = Psu[(m0 + 8) * LDA + kk + 4];
            }
#pragma unroll
            for (int nt = 0; nt < 4; nt++) {
                int n0 = wk * 32 + nt * 8 + g;     // d dim
                uint32_t bv_[2];
                bv_[0] = Vs[(kb2 + t) * LDA + n0];
                bv_[1] = Vs[(kb2 + 4 + t) * LDA + n0];
                mma_tf32(acc[0][nt], ap[0], bv_);
                mma_tf32(acc[1][nt], ap[1], bv_);
            }
        }
    }

    // finalize
    if (shf == 0) linv_sm[srow] = 1.0f / l_r;
    __syncthreads();

    const int b_ = bh >> 4;
    const int h  = bh & 15;
#pragma unroll
    for (int mt = 0; mt < 2; mt++) {
        int r0 = wq * 32 + mt * 16 + g;
        float i0 = linv_sm[r0], i1 = linv_sm[r0 + 8];
        size_t tok0 = (size_t)b_ * SLEN + qblk * 128 + r0;
#pragma unroll
        for (int nt = 0; nt < 4; nt++) {
            int c = wk * 32 + nt * 8 + 2 * t;
            *(float2*)&O[tok0 * EMBED + h * 64 + c] =
                make_float2(acc[mt][nt][0] * i0, acc[mt][nt][1] * i0);
            *(float2*)&O[(tok0 + 8) * EMBED + h * 64 + c] =
                make_float2(acc[mt][nt][2] * i1, acc[mt][nt][3] * i1);
        }
    }
}

// ---------------------------------------------------------------------------
extern "C" void kernel_launch(void* const* d_in, const int* in_sizes, int n_in,
                              void* d_out, int out_size)
{
    const float* x    = (const float*)d_in[0];   // [4,2048,1024]
    const float* Wqkv = (const float*)d_in[1];   // [1024,3072]
    const float* Wout = (const float*)d_in[2];   // [1024,1024]
    float* out = (float*)d_out;                  // [4,2048,1024]

    float *Qp, *Kp, *Vp, *Op;
    cudaGetSymbolAddress((void**)&Qp, g_Q);
    cudaGetSymbolAddress((void**)&Kp, g_K);
    cudaGetSymbolAddress((void**)&Vp, g_V);
    cudaGetSymbolAddress((void**)&Op, g_O);

    // attention dynamic smem: Qs + Ks + Vs + Ss + alpha + linv (u32 units)
    const int attn_smem = (128 * LDA + 64 * LDA + 64 * LDA + 128 * LDA + 256) * 4;
    static bool configured = false;
    if (!configured) {
        cudaFuncSetAttribute(attn_tc_kernel,
                             cudaFuncAttributeMaxDynamicSharedMemorySize, attn_smem);
        configured = true;
    }

    // 1) QKV projection (3xTF32) + de-interleave into Q/K/V [b,h,s,d]
    dim3 g1(QKVN / 128, NTOK / 128);   // (24, 64)
    gemm3x_kernel<0><<<g1, 256>>>(x, Wqkv, nullptr, Qp, Kp, Vp, NTOK, QKVN, EMBED);

    // 2) tensor-core flash attention -> g_O [token, E]
    dim3 g2(SLEN / 128, BATCH * NHEAD); // (16, 64)
    attn_tc_kernel<<<g2, 256, attn_smem>>>(Qp, Kp, Vp, Op);

    // 3) output projection (3xTF32)
    dim3 g3(EMBED / 128, NTOK / 128);  // (8, 64)
    gemm3x_kernel<1><<<g3, 256>>>(Op, Wout, out, nullptr, nullptr, nullptr, NTOK, EMBED, EMBED);
}